// round 15
// baseline (speedup 1.0000x reference)
#include <cuda_runtime.h>
#include <cuda_fp16.h>

// DSA sparse top-k attention.
// q,k,v: (2,8,2048,64) f32; topk_indices/scores: (2,2048,128); out f32.
//
// R14: 72.2us, issue 72%, fma 53%, L1 69% -- hidden wall = 512 F2F.F32.F16
// per thread on the (unreported) conversion pipe. This round: mixed-precision
// fma.rn.f32.f16 (f16 inputs, f32 accumulate; Blackwell FFMA half-selectors)
// removes ALL per-row conversions. q pre-scaled by 1/sqrt(D) and rounded to
// f16 once; weights rounded to f16 once per batch. Structure identical to
// R14: one warp/query, 4-deep pipelined gathers, no smem, no barriers.

#define FULL 0xffffffffu

constexpr int B_ = 2, H_ = 8, S_ = 2048, D_ = 64, VD_ = 64, T_ = 128;
constexpr int THREADS = 128;                            // 4 warps = 4 queries
constexpr int SMALL_ELEMS = B_ * S_ * T_;               // 524288
constexpr size_t KV_ELEMS = (size_t)B_ * H_ * S_ * D_;  // 4,194,304

__device__ __half g_kh[KV_ELEMS];
__device__ __half g_vh[KV_ELEMS];

// cfg: bit1 = indices are in buffer B (else A); bit0 = indices are int64
__device__ int g_idx_cfg;

// Two mixed-precision FMAs: unpack a half2 word, d0 += lo*q0, d1 += hi*q1,
// with f32 accumulators. ptxas folds the mov into FFMA .H0/.H1 selectors.
__device__ __forceinline__ void fma2h(float& d0, float& d1, unsigned int u,
                                      unsigned short q0, unsigned short q1)
{
    asm("{\n\t"
        ".reg .b16 lo, hi;\n\t"
        "mov.b32 {lo, hi}, %2;\n\t"
        "fma.rn.f32.f16 %0, lo, %3, %0;\n\t"
        "fma.rn.f32.f16 %1, hi, %4, %1;\n\t"
        "}"
        : "+f"(d0), "+f"(d1)
        : "r"(u), "h"(q0), "h"(q1));
}

__device__ __forceinline__ unsigned short f2h(float f)
{
    const __half h = __float2half_rn(f);
    return *reinterpret_cast<const unsigned short*>(&h);
}

// Warp-parallel classification of a small buffer's first 128 words.
__device__ __forceinline__ int classify_warp(const void* p, int lane)
{
    const int* w = (const int*)p;
    bool hiz = true, evs = true, alls = true;
    #pragma unroll
    for (int r = 0; r < 4; r++) {
        const int i = lane * 4 + r;
        const int v = w[i];
        const bool small = (v >= 0 && v < S_);
        alls &= small;
        if (i & 1) hiz &= (v == 0);
        else       evs &= small;
    }
    const bool a_hiz = __all_sync(FULL, hiz);
    const bool a_evs = __all_sync(FULL, evs);
    const bool a_all = __all_sync(FULL, alls);
    if (a_hiz && a_evs) return 1;   // int64 indices
    if (a_all)          return 0;   // int32 indices
    return -1;                      // float scores
}

// fp32 -> fp16 K/V conversion + inline probe (block 0, warp 0).
__global__ __launch_bounds__(256)
void convert_kv(const float* __restrict__ k, const float* __restrict__ v,
                const void* __restrict__ pA, const void* __restrict__ pB)
{
    if (blockIdx.x == 0 && threadIdx.x < 32) {
        const int lane = threadIdx.x;
        const int ca = classify_warp(pA, lane);
        int cfg;
        if (ca >= 0) cfg = ca;
        else {
            const int cb = classify_warp(pB, lane);
            cfg = (cb >= 0) ? (2 | cb) : 0;
        }
        if (lane == 0) g_idx_cfg = cfg;
    }

    const size_t i = (size_t)blockIdx.x * blockDim.x + threadIdx.x;
    const float4 a = reinterpret_cast<const float4*>(k)[i];
    const float4 b = reinterpret_cast<const float4*>(v)[i];
    __half2 k0 = __floats2half2_rn(a.x, a.y);
    __half2 k1 = __floats2half2_rn(a.z, a.w);
    __half2 v0 = __floats2half2_rn(b.x, b.y);
    __half2 v1 = __floats2half2_rn(b.z, b.w);
    uint2 ku, vu;
    ku.x = *reinterpret_cast<unsigned int*>(&k0);
    ku.y = *reinterpret_cast<unsigned int*>(&k1);
    vu.x = *reinterpret_cast<unsigned int*>(&v0);
    vu.y = *reinterpret_cast<unsigned int*>(&v1);
    reinterpret_cast<uint2*>(g_kh)[i] = ku;
    reinterpret_cast<uint2*>(g_vh)[i] = vu;
}

// dot of 8 fp16 k-elems against pre-scaled fp16 q slice, f32 accumulate
__device__ __forceinline__ float dot8h(const uint4& r,
                                       const unsigned short* qh)
{
    float d0 = 0.f, d1 = 0.f;
    fma2h(d0, d1, r.x, qh[0], qh[1]);
    fma2h(d0, d1, r.y, qh[2], qh[3]);
    fma2h(d0, d1, r.z, qh[4], qh[5]);
    fma2h(d0, d1, r.w, qh[6], qh[7]);
    return d0 + d1;
}

__global__ __launch_bounds__(THREADS, 9)
void dsa_sparse_attn(const float* __restrict__ q,
                     const void*  __restrict__ pA,
                     const void*  __restrict__ pB,
                     float* __restrict__ out)
{
    const int lane = threadIdx.x & 31;
    const int qi   = blockIdx.x * 4 + (threadIdx.x >> 5);  // (bh*S + s)
    const int s    = qi & (S_ - 1);
    const int bh   = qi >> 11;           // S_ = 2048
    const int b    = bh >> 3;            // H_ = 8

    const float*  qp = q    + ((size_t)bh * S_ + s) * D_;
    const __half* kb = g_kh + (size_t)bh * S_ * D_;
    const __half* vb = g_vh + (size_t)bh * S_ * VD_;

    const int g = lane >> 3;             // group 0..3
    const int l = lane & 7;              // lane in group

    // ---- indices + indexer scores: t = lane + 32*jj lives in reg jj ----
    const int cfg = g_idx_cfg;
    const void*  ibase = (cfg & 2) ? pB : pA;
    const float* tbase = (cfg & 2) ? (const float*)pA : (const float*)pB;
    const size_t sb = ((size_t)b * S_ + s) * T_;

    int   idxv[4];
    float tsv[4];
    if (cfg & 1) {
        const long long* ip = (const long long*)ibase + sb;
        #pragma unroll
        for (int jj = 0; jj < 4; jj++)
            idxv[jj] = ((int)ip[lane + 32 * jj]) & (S_ - 1);
    } else {
        const int* ip = (const int*)ibase + sb;
        #pragma unroll
        for (int jj = 0; jj < 4; jj++)
            idxv[jj] = ip[lane + 32 * jj] & (S_ - 1);
    }
    #pragma unroll
    for (int jj = 0; jj < 4; jj++)
        tsv[jj] = tbase[sb + lane + 32 * jj];

    // q slice: 8 dims [l*8, l*8+8), pre-scaled by 1/sqrt(D)=0.125 (exact,
    // power of two) and rounded once to f16.
    unsigned short qh[8];
    {
        const float4 q0 = *reinterpret_cast<const float4*>(qp + l * 8);
        const float4 q1 = *reinterpret_cast<const float4*>(qp + l * 8 + 4);
        qh[0] = f2h(q0.x * 0.125f); qh[1] = f2h(q0.y * 0.125f);
        qh[2] = f2h(q0.z * 0.125f); qh[3] = f2h(q0.w * 0.125f);
        qh[4] = f2h(q1.x * 0.125f); qh[5] = f2h(q1.y * 0.125f);
        qh[6] = f2h(q1.z * 0.125f); qh[7] = f2h(q1.w * 0.125f);
    }

    // ---------------- scores: 4 batches of 32 rows ----------------
    // 4-deep pipelined gather; butterfly leaves score for row 32*jj+lane
    // on this lane (group g handles rows g*8+j, and g*8+l == lane).
    float x[4];
    #pragma unroll
    for (int jj = 0; jj < 4; jj++) {
        float vals[8];
        uint4 kr[4];
        #pragma unroll
        for (int j = 0; j < 4; j++) {
            const int ridx = __shfl_sync(FULL, idxv[jj], g * 8 + j);
            kr[j] = *reinterpret_cast<const uint4*>(
                        kb + (size_t)ridx * D_ + l * 8);
        }
        uint4 kr2[4];
        #pragma unroll
        for (int j = 0; j < 4; j++) {
            const int ridx = __shfl_sync(FULL, idxv[jj], g * 8 + 4 + j);
            kr2[j] = *reinterpret_cast<const uint4*>(
                        kb + (size_t)ridx * D_ + l * 8);
        }
        #pragma unroll
        for (int j = 0; j < 4; j++) vals[j] = dot8h(kr[j], qh);
        #pragma unroll
        for (int j = 0; j < 4; j++) vals[4 + j] = dot8h(kr2[j], qh);

        #pragma unroll
        for (int off = 4; off > 0; off >>= 1) {
            #pragma unroll
            for (int j = 0; j < off; j++) {
                const float a  = vals[j];
                const float bb = vals[j + off];
                const bool  hi = (l & off) != 0;
                const float mine  = hi ? bb : a;
                float       other = hi ? a  : bb;
                other = __shfl_xor_sync(FULL, other, off);
                vals[j] = mine + other;
            }
        }
        x[jj] = vals[0];                 // 0.125 scale folded into q
    }

    // ---------------- softmax + reweight + renormalize (warp-only) ------
    float m = fmaxf(fmaxf(x[0], x[1]), fmaxf(x[2], x[3]));
    #pragma unroll
    for (int off = 16; off > 0; off >>= 1)
        m = fmaxf(m, __shfl_xor_sync(FULL, m, off));

    float e[4], se = 0.f, swt = 0.f;
    #pragma unroll
    for (int jj = 0; jj < 4; jj++) {
        e[jj] = __expf(x[jj] - m);
        se  += e[jj];
        swt += e[jj] * tsv[jj];
    }
    #pragma unroll
    for (int off = 16; off > 0; off >>= 1) {
        se  += __shfl_xor_sync(FULL, se,  off);
        swt += __shfl_xor_sync(FULL, swt, off);
    }

    // p = softmax * ts ; final = p / (sum(p) + 1e-12)   (faithful to ref)
    const float denom = swt / se + 1e-12f;
    int whb[4];                          // final weights as f16 bits
    #pragma unroll
    for (int jj = 0; jj < 4; jj++)
        whb[jj] = (int)f2h(((e[jj] / se) * tsv[jj]) / denom);

    // ---------------- output: sum_t w_t * v_gathered (pipelined) --------
    float acc[8] = {0.f, 0.f, 0.f, 0.f, 0.f, 0.f, 0.f, 0.f};
    #pragma unroll
    for (int jj = 0; jj < 4; jj++) {
        uint4 vr[4];
        unsigned short wr[4];
        #pragma unroll
        for (int j = 0; j < 4; j++) {
            const int src  = g * 8 + j;
            const int ridx = __shfl_sync(FULL, idxv[jj], src);
            vr[j] = *reinterpret_cast<const uint4*>(
                        vb + (size_t)ridx * VD_ + l * 8);
            wr[j] = (unsigned short)__shfl_sync(FULL, whb[jj], src);
        }
        uint4 vr2[4];
        unsigned short wr2[4];
        #pragma unroll
        for (int j = 0; j < 4; j++) {
            const int src  = g * 8 + 4 + j;
            const int ridx = __shfl_sync(FULL, idxv[jj], src);
            vr2[j] = *reinterpret_cast<const uint4*>(
                        vb + (size_t)ridx * VD_ + l * 8);
            wr2[j] = (unsigned short)__shfl_sync(FULL, whb[jj], src);
        }
        #pragma unroll
        for (int j = 0; j < 4; j++) {
            fma2h(acc[0], acc[1], vr[j].x, wr[j], wr[j]);
            fma2h(acc[2], acc[3], vr[j].y, wr[j], wr[j]);
            fma2h(acc[4], acc[5], vr[j].z, wr[j], wr[j]);
            fma2h(acc[6], acc[7], vr[j].w, wr[j], wr[j]);
        }
        #pragma unroll
        for (int j = 0; j < 4; j++) {
            fma2h(acc[0], acc[1], vr2[j].x, wr2[j], wr2[j]);
            fma2h(acc[2], acc[3], vr2[j].y, wr2[j], wr2[j]);
            fma2h(acc[4], acc[5], vr2[j].z, wr2[j], wr2[j]);
            fma2h(acc[6], acc[7], vr2[j].w, wr2[j], wr2[j]);
        }
    }
    // Combine the 4 groups (same dim slice l across g)
    #pragma unroll
    for (int i = 0; i < 8; i++) {
        acc[i] += __shfl_down_sync(FULL, acc[i], 8);
        acc[i] += __shfl_down_sync(FULL, acc[i], 16);
    }

    if (lane < 8) {
        float* op = out + ((size_t)bh * S_ + s) * VD_ + lane * 8;
        *reinterpret_cast<float4*>(op)     = make_float4(acc[0], acc[1],
                                                         acc[2], acc[3]);
        *reinterpret_cast<float4*>(op + 4) = make_float4(acc[4], acc[5],
                                                         acc[6], acc[7]);
    }
}

extern "C" void kernel_launch(void* const* d_in, const int* in_sizes, int n_in,
                              void* d_out, int out_size)
{
    const float* big[3] = {nullptr, nullptr, nullptr};
    const void*  small[2] = {nullptr, nullptr};
    int nb = 0, ns = 0;
    for (int i = 0; i < n_in; i++) {
        if (in_sizes[i] == SMALL_ELEMS) { if (ns < 2) small[ns++] = d_in[i]; }
        else                            { if (nb < 3) big[nb++]   = (const float*)d_in[i]; }
    }
    if (nb != 3 || ns != 2) {
        big[0] = (const float*)d_in[0];
        big[1] = (const float*)d_in[1];
        big[2] = (const float*)d_in[2];
        small[0] = d_in[3];
        small[1] = d_in[4];
    }

    convert_kv<<<(int)(KV_ELEMS / 4 / 256), 256>>>(big[1], big[2],
                                                   small[0], small[1]);
    dsa_sparse_attn<<<B_ * H_ * S_ / 4, THREADS>>>(
        big[0], small[0], small[1], (float*)d_out);
}

// round 16
// speedup vs baseline: 1.0510x; 1.0510x over previous
#include <cuda_runtime.h>
#include <cuda_fp16.h>

// DSA sparse top-k attention.
// q,k,v: (2,8,2048,64) f32; topk_indices/scores: (2,2048,128); out f32.
//
// R14 = 72.2us (best). R15 (mixed-precision FMA) regressed despite -500
// issue slots -> kernel is MIO/LSU-stream bound (gather LDG + ~155 SHFL),
// not fma/issue bound. This round: R14 arithmetic restored; V phase packs
// (idx | w_f16<<16) so each row needs ONE shuffle instead of two
// (-32 SHFL/thread), unpacked with cheap ALU. One warp per query, 4-deep
// pipelined gathers, no smem, no barriers, fp16 K/V scratch.

#define FULL 0xffffffffu

constexpr int B_ = 2, H_ = 8, S_ = 2048, D_ = 64, VD_ = 64, T_ = 128;
constexpr int THREADS = 128;                            // 4 warps = 4 queries
constexpr int SMALL_ELEMS = B_ * S_ * T_;               // 524288
constexpr size_t KV_ELEMS = (size_t)B_ * H_ * S_ * D_;  // 4,194,304

__device__ __half g_kh[KV_ELEMS];
__device__ __half g_vh[KV_ELEMS];

// cfg: bit1 = indices are in buffer B (else A); bit0 = indices are int64
__device__ int g_idx_cfg;

__device__ __forceinline__ unsigned short f2h(float f)
{
    const __half h = __float2half_rn(f);
    return *reinterpret_cast<const unsigned short*>(&h);
}

// Warp-parallel classification of a small buffer's first 128 words.
__device__ __forceinline__ int classify_warp(const void* p, int lane)
{
    const int* w = (const int*)p;
    bool hiz = true, evs = true, alls = true;
    #pragma unroll
    for (int r = 0; r < 4; r++) {
        const int i = lane * 4 + r;
        const int v = w[i];
        const bool small = (v >= 0 && v < S_);
        alls &= small;
        if (i & 1) hiz &= (v == 0);
        else       evs &= small;
    }
    const bool a_hiz = __all_sync(FULL, hiz);
    const bool a_evs = __all_sync(FULL, evs);
    const bool a_all = __all_sync(FULL, alls);
    if (a_hiz && a_evs) return 1;   // int64 indices
    if (a_all)          return 0;   // int32 indices
    return -1;                      // float scores
}

// fp32 -> fp16 K/V conversion + inline probe (block 0, warp 0).
__global__ __launch_bounds__(256)
void convert_kv(const float* __restrict__ k, const float* __restrict__ v,
                const void* __restrict__ pA, const void* __restrict__ pB)
{
    if (blockIdx.x == 0 && threadIdx.x < 32) {
        const int lane = threadIdx.x;
        const int ca = classify_warp(pA, lane);
        int cfg;
        if (ca >= 0) cfg = ca;
        else {
            const int cb = classify_warp(pB, lane);
            cfg = (cb >= 0) ? (2 | cb) : 0;
        }
        if (lane == 0) g_idx_cfg = cfg;
    }

    const size_t i = (size_t)blockIdx.x * blockDim.x + threadIdx.x;
    const float4 a = reinterpret_cast<const float4*>(k)[i];
    const float4 b = reinterpret_cast<const float4*>(v)[i];
    __half2 k0 = __floats2half2_rn(a.x, a.y);
    __half2 k1 = __floats2half2_rn(a.z, a.w);
    __half2 v0 = __floats2half2_rn(b.x, b.y);
    __half2 v1 = __floats2half2_rn(b.z, b.w);
    uint2 ku, vu;
    ku.x = *reinterpret_cast<unsigned int*>(&k0);
    ku.y = *reinterpret_cast<unsigned int*>(&k1);
    vu.x = *reinterpret_cast<unsigned int*>(&v0);
    vu.y = *reinterpret_cast<unsigned int*>(&v1);
    reinterpret_cast<uint2*>(g_kh)[i] = ku;
    reinterpret_cast<uint2*>(g_vh)[i] = vu;
}

__device__ __forceinline__ float dot8(const uint4& r, const float* qv)
{
    const __half2* h2 = reinterpret_cast<const __half2*>(&r);
    const float2 f0 = __half22float2(h2[0]);
    const float2 f1 = __half22float2(h2[1]);
    const float2 f2 = __half22float2(h2[2]);
    const float2 f3 = __half22float2(h2[3]);
    float d;
    d  = f0.x * qv[0] + f0.y * qv[1];
    d += f1.x * qv[2] + f1.y * qv[3];
    d += f2.x * qv[4] + f2.y * qv[5];
    d += f3.x * qv[6] + f3.y * qv[7];
    return d;
}

__global__ __launch_bounds__(THREADS, 9)
void dsa_sparse_attn(const float* __restrict__ q,
                     const void*  __restrict__ pA,
                     const void*  __restrict__ pB,
                     float* __restrict__ out)
{
    const int lane = threadIdx.x & 31;
    const int qi   = blockIdx.x * 4 + (threadIdx.x >> 5);  // (bh*S + s)
    const int s    = qi & (S_ - 1);
    const int bh   = qi >> 11;           // S_ = 2048
    const int b    = bh >> 3;            // H_ = 8

    const float*  qp = q    + ((size_t)bh * S_ + s) * D_;
    const __half* kb = g_kh + (size_t)bh * S_ * D_;
    const __half* vb = g_vh + (size_t)bh * S_ * VD_;

    const int g = lane >> 3;             // group 0..3
    const int l = lane & 7;              // lane in group

    // ---- indices + indexer scores: t = lane + 32*jj lives in reg jj ----
    const int cfg = g_idx_cfg;
    const void*  ibase = (cfg & 2) ? pB : pA;
    const float* tbase = (cfg & 2) ? (const float*)pA : (const float*)pB;
    const size_t sb = ((size_t)b * S_ + s) * T_;

    int   idxv[4];
    float tsv[4];
    if (cfg & 1) {
        const long long* ip = (const long long*)ibase + sb;
        #pragma unroll
        for (int jj = 0; jj < 4; jj++)
            idxv[jj] = ((int)ip[lane + 32 * jj]) & (S_ - 1);
    } else {
        const int* ip = (const int*)ibase + sb;
        #pragma unroll
        for (int jj = 0; jj < 4; jj++)
            idxv[jj] = ip[lane + 32 * jj] & (S_ - 1);
    }
    #pragma unroll
    for (int jj = 0; jj < 4; jj++)
        tsv[jj] = tbase[sb + lane + 32 * jj];

    // q slice: 8 dims [l*8, l*8+8)
    float qv[8];
    {
        const float4 q0 = *reinterpret_cast<const float4*>(qp + l * 8);
        const float4 q1 = *reinterpret_cast<const float4*>(qp + l * 8 + 4);
        qv[0] = q0.x; qv[1] = q0.y; qv[2] = q0.z; qv[3] = q0.w;
        qv[4] = q1.x; qv[5] = q1.y; qv[6] = q1.z; qv[7] = q1.w;
    }

    // ---------------- scores: 4 batches of 32 rows ----------------
    // 4-deep pipelined gather; butterfly leaves score for row 32*jj+lane
    // on this lane (group g handles rows g*8+j, and g*8+l == lane).
    float x[4];
    #pragma unroll
    for (int jj = 0; jj < 4; jj++) {
        float vals[8];
        uint4 kr[4];
        #pragma unroll
        for (int j = 0; j < 4; j++) {
            const int ridx = __shfl_sync(FULL, idxv[jj], g * 8 + j);
            kr[j] = *reinterpret_cast<const uint4*>(
                        kb + (size_t)ridx * D_ + l * 8);
        }
        uint4 kr2[4];
        #pragma unroll
        for (int j = 0; j < 4; j++) {
            const int ridx = __shfl_sync(FULL, idxv[jj], g * 8 + 4 + j);
            kr2[j] = *reinterpret_cast<const uint4*>(
                        kb + (size_t)ridx * D_ + l * 8);
        }
        #pragma unroll
        for (int j = 0; j < 4; j++) vals[j] = dot8(kr[j], qv);
        #pragma unroll
        for (int j = 0; j < 4; j++) vals[4 + j] = dot8(kr2[j], qv);

        #pragma unroll
        for (int off = 4; off > 0; off >>= 1) {
            #pragma unroll
            for (int j = 0; j < off; j++) {
                const float a  = vals[j];
                const float bb = vals[j + off];
                const bool  hi = (l & off) != 0;
                const float mine  = hi ? bb : a;
                float       other = hi ? a  : bb;
                other = __shfl_xor_sync(FULL, other, off);
                vals[j] = mine + other;
            }
        }
        x[jj] = vals[0] * 0.125f;        // * D^-0.5
    }

    // ---------------- softmax + reweight + renormalize (warp-only) ------
    float m = fmaxf(fmaxf(x[0], x[1]), fmaxf(x[2], x[3]));
    #pragma unroll
    for (int off = 16; off > 0; off >>= 1)
        m = fmaxf(m, __shfl_xor_sync(FULL, m, off));

    float e[4], se = 0.f, swt = 0.f;
    #pragma unroll
    for (int jj = 0; jj < 4; jj++) {
        e[jj] = __expf(x[jj] - m);
        se  += e[jj];
        swt += e[jj] * tsv[jj];
    }
    #pragma unroll
    for (int off = 16; off > 0; off >>= 1) {
        se  += __shfl_xor_sync(FULL, se,  off);
        swt += __shfl_xor_sync(FULL, swt, off);
    }

    // p = softmax * ts ; final = p / (sum(p) + 1e-12)   (faithful to ref)
    // Pack (idx | w_f16 << 16): ONE shuffle per row in the V phase.
    const float denom = swt / se + 1e-12f;
    int pw[4];
    #pragma unroll
    for (int jj = 0; jj < 4; jj++) {
        const float wfin = ((e[jj] / se) * tsv[jj]) / denom;
        pw[jj] = idxv[jj] | ((int)f2h(wfin) << 16);
    }

    // ---------------- output: sum_t w_t * v_gathered (pipelined) --------
    float acc[8] = {0.f, 0.f, 0.f, 0.f, 0.f, 0.f, 0.f, 0.f};
    #pragma unroll
    for (int jj = 0; jj < 4; jj++) {
        uint4 vr[4];
        float wr[4];
        #pragma unroll
        for (int j = 0; j < 4; j++) {
            const int pk = __shfl_sync(FULL, pw[jj], g * 8 + j);
            vr[j] = *reinterpret_cast<const uint4*>(
                        vb + (size_t)(pk & 0xFFFF) * VD_ + l * 8);
            wr[j] = __half2float(
                        __ushort_as_half((unsigned short)((unsigned)pk >> 16)));
        }
        uint4 vr2[4];
        float wr2[4];
        #pragma unroll
        for (int j = 0; j < 4; j++) {
            const int pk = __shfl_sync(FULL, pw[jj], g * 8 + 4 + j);
            vr2[j] = *reinterpret_cast<const uint4*>(
                        vb + (size_t)(pk & 0xFFFF) * VD_ + l * 8);
            wr2[j] = __half2float(
                        __ushort_as_half((unsigned short)((unsigned)pk >> 16)));
        }
        #pragma unroll
        for (int j = 0; j < 4; j++) {
            const __half2* h2 = reinterpret_cast<const __half2*>(&vr[j]);
            #pragma unroll
            for (int i = 0; i < 4; i++) {
                const float2 f = __half22float2(h2[i]);
                acc[2 * i + 0] += wr[j] * f.x;
                acc[2 * i + 1] += wr[j] * f.y;
            }
        }
        #pragma unroll
        for (int j = 0; j < 4; j++) {
            const __half2* h2 = reinterpret_cast<const __half2*>(&vr2[j]);
            #pragma unroll
            for (int i = 0; i < 4; i++) {
                const float2 f = __half22float2(h2[i]);
                acc[2 * i + 0] += wr2[j] * f.x;
                acc[2 * i + 1] += wr2[j] * f.y;
            }
        }
    }
    // Combine the 4 groups (same dim slice l across g)
    #pragma unroll
    for (int i = 0; i < 8; i++) {
        acc[i] += __shfl_down_sync(FULL, acc[i], 8);
        acc[i] += __shfl_down_sync(FULL, acc[i], 16);
    }

    if (lane < 8) {
        float* op = out + ((size_t)bh * S_ + s) * VD_ + lane * 8;
        *reinterpret_cast<float4*>(op)     = make_float4(acc[0], acc[1],
                                                         acc[2], acc[3]);
        *reinterpret_cast<float4*>(op + 4) = make_float4(acc[4], acc[5],
                                                         acc[6], acc[7]);
    }
}

extern "C" void kernel_launch(void* const* d_in, const int* in_sizes, int n_in,
                              void* d_out, int out_size)
{
    const float* big[3] = {nullptr, nullptr, nullptr};
    const void*  small[2] = {nullptr, nullptr};
    int nb = 0, ns = 0;
    for (int i = 0; i < n_in; i++) {
        if (in_sizes[i] == SMALL_ELEMS) { if (ns < 2) small[ns++] = d_in[i]; }
        else                            { if (nb < 3) big[nb++]   = (const float*)d_in[i]; }
    }
    if (nb != 3 || ns != 2) {
        big[0] = (const float*)d_in[0];
        big[1] = (const float*)d_in[1];
        big[2] = (const float*)d_in[2];
        small[0] = d_in[3];
        small[1] = d_in[4];
    }

    convert_kv<<<(int)(KV_ELEMS / 4 / 256), 256>>>(big[1], big[2],
                                                   small[0], small[1]);
    dsa_sparse_attn<<<B_ * H_ * S_ / 4, THREADS>>>(
        big[0], small[0], small[1], (float*)d_out);
}